// round 2
// baseline (speedup 1.0000x reference)
#include <cuda_runtime.h>
#include <math.h>

#define Bb 4
#define Mm 2048
#define Cc 512
#define Hh 8
#define DQKd 16
#define DVd 64

// Scratch for projections (no cudaMalloc allowed)
__device__ float g_Q[Bb * Hh * Mm * DQKd];   // (bh, m, 16)
__device__ float g_K[Bb * Hh * Mm * DQKd];   // (bh, m, 16)
__device__ float g_V[Bb * Hh * Mm * DVd];    // (bh, m, 64)

// ---------------------------------------------------------------------------
// Kernel 1: fused QKV projection.  out(8192 x 768) = x(8192 x 512) @ [Wq|Wk|Wv]
// BM=128, BN=64, BK=16; 128 threads; 8x8 register tile (1 B shared / FMA).
// ---------------------------------------------------------------------------
__global__ __launch_bounds__(128) void proj_kernel(
    const float* __restrict__ x,
    const float* __restrict__ Wq, const float* __restrict__ bq,
    const float* __restrict__ Wk, const float* __restrict__ bk,
    const float* __restrict__ Wv, const float* __restrict__ bv)
{
    __shared__ float As[16][128];   // transposed x tile
    __shared__ float Bs[16][64];

    const int row0 = blockIdx.x * 128;
    const int col0 = blockIdx.y * 64;
    const int tid = threadIdx.x;
    const int mg = tid >> 3;    // 0..15
    const int ng = tid & 7;     // 0..7

    const float* W; const float* bias; int ldw; int jofs;
    if (col0 < 128)      { W = Wq; bias = bq; ldw = 128; jofs = col0;       }
    else if (col0 < 256) { W = Wk; bias = bk; ldw = 128; jofs = col0 - 128; }
    else                 { W = Wv; bias = bv; ldw = 512; jofs = col0 - 256; }

    float acc[8][8] = {};

    const int blr = tid >> 3;        // B load row 0..15
    const int blc = (tid & 7) * 8;   // B load col

    for (int k0 = 0; k0 < Cc; k0 += 16) {
        // A tile: one row per thread, transposed into As
        const float* xr = &x[(size_t)(row0 + tid) * Cc + k0];
#pragma unroll
        for (int q = 0; q < 4; q++) {
            float4 v = *(const float4*)(xr + q * 4);
            As[q * 4 + 0][tid] = v.x;
            As[q * 4 + 1][tid] = v.y;
            As[q * 4 + 2][tid] = v.z;
            As[q * 4 + 3][tid] = v.w;
        }
        // B tile: 8 floats per thread
        const float* wr = &W[(size_t)(k0 + blr) * ldw + jofs + blc];
        *(float4*)&Bs[blr][blc]     = *(const float4*)wr;
        *(float4*)&Bs[blr][blc + 4] = *(const float4*)(wr + 4);
        __syncthreads();
#pragma unroll
        for (int kk = 0; kk < 16; kk++) {
            float4 a0 = *(const float4*)&As[kk][mg * 8];
            float4 a1 = *(const float4*)&As[kk][mg * 8 + 4];
            float4 b0 = *(const float4*)&Bs[kk][ng * 8];
            float4 b1 = *(const float4*)&Bs[kk][ng * 8 + 4];
            float ar[8] = {a0.x, a0.y, a0.z, a0.w, a1.x, a1.y, a1.z, a1.w};
            float br[8] = {b0.x, b0.y, b0.z, b0.w, b1.x, b1.y, b1.z, b1.w};
#pragma unroll
            for (int i = 0; i < 8; i++)
#pragma unroll
                for (int j = 0; j < 8; j++)
                    acc[i][j] = fmaf(ar[i], br[j], acc[i][j]);
        }
        __syncthreads();
    }

    // epilogue: add bias, scatter into head-major Q/K/V scratch
#pragma unroll
    for (int j = 0; j < 8; j++) {
        const int jg = col0 + ng * 8 + j;
        const float bval = bias[jofs + ng * 8 + j];
#pragma unroll
        for (int i = 0; i < 8; i++) {
            const int rg = row0 + mg * 8 + i;
            const int b  = rg >> 11;        // / Mm
            const int m  = rg & (Mm - 1);
            const float v = acc[i][j] + bval;
            if (jg < 128) {
                g_Q[(((size_t)(b * Hh + (jg >> 4)) * Mm) + m) * DQKd + (jg & 15)] = v;
            } else if (jg < 256) {
                const int jj = jg - 128;
                g_K[(((size_t)(b * Hh + (jj >> 4)) * Mm) + m) * DQKd + (jj & 15)] = v;
            } else {
                const int jj = jg - 256;
                g_V[(((size_t)(b * Hh + (jj >> 6)) * Mm) + m) * DVd + (jj & 63)] = v;
            }
        }
    }
}

// ---------------------------------------------------------------------------
// Kernel 2: fused attention. BM=128 q-rows, BN=32 keys/iter, 128 threads.
// PV thread tile 8x8 (1 B shared / FMA). Rescale-free streaming:
// w = mask * exp(relu(q.k * 0.25)); o = gamma * (sum w v)/(sum w).
// Ws columns rotated by 2*mg to kill store bank conflicts.
// ---------------------------------------------------------------------------
__global__ __launch_bounds__(128, 4) void attn_kernel(
    const int* __restrict__ mask, const float* __restrict__ gamma,
    float* __restrict__ out)
{
    const int BM = 128, BN = 32;
    __shared__ float QT[DQKd][BM];       // transposed Q tile (16x128)
    __shared__ float KT[DQKd][BN];       // transposed K tile (16x32)
    __shared__ float Vs[BN][DVd];        // V tile (32x64)
    __shared__ float Ws[BM][BN + 1];     // weights, column-rotated
    __shared__ float rowTot[BM];
    __shared__ float wm[BN];

    const int bh = blockIdx.x >> 4;      // 0..31
    const int mt = blockIdx.x & 15;      // 0..15
    const int b  = bh >> 3;
    const int h  = bh & 7;
    const int m0 = mt * BM;
    const int tid = threadIdx.x;
    const int mg = tid >> 3;             // 0..15
    const int ng = tid & 7;              // 0..7 (also d-group in PV)

    const float* Qp = g_Q + (size_t)bh * Mm * DQKd;
    const float* Kp = g_K + (size_t)bh * Mm * DQKd;
    const float* Vp = g_V + (size_t)bh * Mm * DVd;

    {   // load Q tile transposed: one row per thread
        const float* qr = Qp + (size_t)(m0 + tid) * DQKd;
#pragma unroll
        for (int q = 0; q < 4; q++) {
            float4 v = *(const float4*)(qr + q * 4);
            QT[q * 4 + 0][tid] = v.x;
            QT[q * 4 + 1][tid] = v.y;
            QT[q * 4 + 2][tid] = v.z;
            QT[q * 4 + 3][tid] = v.w;
        }
    }
    rowTot[tid] = 0.0f;

    float acc[8][8] = {};
    float rsum[8] = {};
    const int crot = 2 * (mg & 3);       // column rotation for Ws stores

    for (int nt = 0; nt < Mm / BN; nt++) {
        const int n0 = nt * BN;
        __syncthreads();   // prev PV done; QT visible on iter 0
        {   // K tile transposed: 4 threads per row
            const int r = tid >> 2, kq = tid & 3;
            float4 v = *(const float4*)&Kp[(size_t)(n0 + r) * DQKd + kq * 4];
            KT[kq * 4 + 0][r] = v.x;
            KT[kq * 4 + 1][r] = v.y;
            KT[kq * 4 + 2][r] = v.z;
            KT[kq * 4 + 3][r] = v.w;
        }
        {   // V tile: 4 threads per row, 16 floats each
            const int r = tid >> 2, cq = (tid & 3) * 16;
            const float4* vp = (const float4*)&Vp[(size_t)(n0 + r) * DVd + cq];
            float4* vd = (float4*)&Vs[r][cq];
            vd[0] = vp[0]; vd[1] = vp[1]; vd[2] = vp[2]; vd[3] = vp[3];
        }
        if (tid < BN) wm[tid] = (float)mask[b * Mm + n0 + tid];
        __syncthreads();

        // S = Q K^T : 8x4 per thread
        float s[8][4] = {};
#pragma unroll
        for (int kk = 0; kk < DQKd; kk++) {
            float4 a0 = *(const float4*)&QT[kk][mg * 8];
            float4 a1 = *(const float4*)&QT[kk][mg * 8 + 4];
            float4 bq = *(const float4*)&KT[kk][ng * 4];
            float ar[8] = {a0.x, a0.y, a0.z, a0.w, a1.x, a1.y, a1.z, a1.w};
            float br[4] = {bq.x, bq.y, bq.z, bq.w};
#pragma unroll
            for (int i = 0; i < 8; i++)
#pragma unroll
                for (int j = 0; j < 4; j++)
                    s[i][j] = fmaf(ar[i], br[j], s[i][j]);
        }

        // w = mask * exp(relu(s/4)); store into rotated Ws columns
#pragma unroll
        for (int j = 0; j < 4; j++) {
            const int c = ng * 4 + j;
            const int p = (c + crot) & 31;
            const float mk = wm[c];
#pragma unroll
            for (int i = 0; i < 8; i++) {
                float w = mk * __expf(fmaxf(s[i][j] * 0.25f, 0.0f));
                rsum[i] += w;
                Ws[mg * 8 + i][p] = w;
            }
        }
        __syncthreads();

        // O += W V : 8x8 per thread
#pragma unroll 4
        for (int c = 0; c < BN; c++) {
            const int p = (c + crot) & 31;   // reader's own rows share its mg
            float4 v0 = *(const float4*)&Vs[c][ng * 8];
            float4 v1 = *(const float4*)&Vs[c][ng * 8 + 4];
#pragma unroll
            for (int i = 0; i < 8; i++) {
                const float w = Ws[mg * 8 + i][p];
                acc[i][0] = fmaf(w, v0.x, acc[i][0]);
                acc[i][1] = fmaf(w, v0.y, acc[i][1]);
                acc[i][2] = fmaf(w, v0.z, acc[i][2]);
                acc[i][3] = fmaf(w, v0.w, acc[i][3]);
                acc[i][4] = fmaf(w, v1.x, acc[i][4]);
                acc[i][5] = fmaf(w, v1.y, acc[i][5]);
                acc[i][6] = fmaf(w, v1.z, acc[i][6]);
                acc[i][7] = fmaf(w, v1.w, acc[i][7]);
            }
        }
    }

    // reduce row sums across the 8 ng-groups sharing each m-row
#pragma unroll
    for (int i = 0; i < 8; i++) atomicAdd(&rowTot[mg * 8 + i], rsum[i]);
    __syncthreads();

    const float g = *gamma;
#pragma unroll
    for (int i = 0; i < 8; i++) {
        const int m = m0 + mg * 8 + i;
        const float inv = g / rowTot[mg * 8 + i];
        float4 o0, o1;
        o0.x = acc[i][0] * inv; o0.y = acc[i][1] * inv;
        o0.z = acc[i][2] * inv; o0.w = acc[i][3] * inv;
        o1.x = acc[i][4] * inv; o1.y = acc[i][5] * inv;
        o1.z = acc[i][6] * inv; o1.w = acc[i][7] * inv;
        float* op = &out[((size_t)b * Mm + m) * Cc + h * DVd + ng * 8];
        *(float4*)op       = o0;
        *(float4*)(op + 4) = o1;
    }
}

// ---------------------------------------------------------------------------
extern "C" void kernel_launch(void* const* d_in, const int* in_sizes, int n_in,
                              void* d_out, int out_size)
{
    const float* x     = (const float*)d_in[0];
    const int*   mask  = (const int*)  d_in[1];
    const float* Wq    = (const float*)d_in[2];
    const float* bq    = (const float*)d_in[3];
    const float* Wk    = (const float*)d_in[4];
    const float* bk    = (const float*)d_in[5];
    const float* Wv    = (const float*)d_in[6];
    const float* bv    = (const float*)d_in[7];
    const float* gamma = (const float*)d_in[8];
    float* out = (float*)d_out;

    dim3 pg((Bb * Mm) / 128, (Cc / 4 + Cc / 4 + Cc) / 64);  // (64, 12)
    proj_kernel<<<pg, 128>>>(x, Wq, bq, Wk, bk, Wv, bv);

    dim3 ag(Bb * Hh * (Mm / 128));                          // 512
    attn_kernel<<<ag, 128>>>(mask, gamma, out);
}

// round 4
// speedup vs baseline: 3.0508x; 3.0508x over previous
#include <cuda_runtime.h>
#include <cuda_fp16.h>
#include <cstdint>
#include <math.h>

#define Bb 4
#define Mm 2048
#define Cc 512
#define Hh 8
#define BHt 32

// fp16 staging produced by proj kernel
__device__ __half g_Qh[BHt * Mm * 16];    // (bh, m, 16)  pre-scaled by 0.25
__device__ __half g_Kh[BHt * Mm * 16];    // (bh, m, 16)
__device__ __half g_VTh[BHt * 64 * Mm];   // (bh, d, m)   transposed V

__device__ __forceinline__ uint32_t smem_u32(const void* p) {
    uint32_t a;
    asm("{ .reg .u64 t; cvta.to.shared.u64 t, %1; cvt.u32.u64 %0, t; }"
        : "=r"(a) : "l"(p));
    return a;
}
__device__ __forceinline__ void ldm4(uint32_t r[4], uint32_t addr) {
    asm volatile("ldmatrix.sync.aligned.m8n8.x4.shared.b16 {%0,%1,%2,%3}, [%4];"
                 : "=r"(r[0]), "=r"(r[1]), "=r"(r[2]), "=r"(r[3]) : "r"(addr));
}
__device__ __forceinline__ void mma16816(float c[4], const uint32_t a[4],
                                         uint32_t b0, uint32_t b1) {
    asm volatile("mma.sync.aligned.m16n8k16.row.col.f32.f16.f16.f32 "
                 "{%0,%1,%2,%3}, {%4,%5,%6,%7}, {%8,%9}, {%0,%1,%2,%3};"
                 : "+f"(c[0]), "+f"(c[1]), "+f"(c[2]), "+f"(c[3])
                 : "r"(a[0]), "r"(a[1]), "r"(a[2]), "r"(a[3]), "r"(b0), "r"(b1));
}

// ---------------------------------------------------------------------------
// Kernel 1: fused QKV projection (fp32 math) -> fp16 staging.
// BM=64, BN=64, BK=16; 256 threads; 4x4 register tile. (R1-proven structure)
// ---------------------------------------------------------------------------
__global__ __launch_bounds__(256) void proj_kernel(
    const float* __restrict__ x,
    const float* __restrict__ Wq, const float* __restrict__ bq,
    const float* __restrict__ Wk, const float* __restrict__ bk,
    const float* __restrict__ Wv, const float* __restrict__ bv)
{
    const int BK = 16;
    __shared__ float As[BK][68];
    __shared__ float Bs[BK][68];

    const int row0 = blockIdx.x * 64;
    const int col0 = blockIdx.y * 64;
    const int tid = threadIdx.x;
    const int tx = tid & 15;
    const int ty = tid >> 4;

    const float* W; const float* bias; int ldw; int jofs;
    if (col0 < 128)      { W = Wq; bias = bq; ldw = 128; jofs = col0;       }
    else if (col0 < 256) { W = Wk; bias = bk; ldw = 128; jofs = col0 - 128; }
    else                 { W = Wv; bias = bv; ldw = 512; jofs = col0 - 256; }

    float acc[4][4] = {};

    const int lr  = tid >> 2;
    const int lkq = tid & 3;
    const int lkk = tid >> 4;
    const int lcq = tid & 15;

    for (int k0 = 0; k0 < Cc; k0 += BK) {
        float4 av = *(const float4*)&x[(size_t)(row0 + lr) * Cc + k0 + lkq * 4];
        As[lkq * 4 + 0][lr] = av.x;
        As[lkq * 4 + 1][lr] = av.y;
        As[lkq * 4 + 2][lr] = av.z;
        As[lkq * 4 + 3][lr] = av.w;
        float4 bv4 = *(const float4*)&W[(size_t)(k0 + lkk) * ldw + jofs + lcq * 4];
        *(float4*)&Bs[lkk][lcq * 4] = bv4;
        __syncthreads();
#pragma unroll
        for (int kk = 0; kk < BK; kk++) {
            float4 a = *(const float4*)&As[kk][ty * 4];
            float4 b = *(const float4*)&Bs[kk][tx * 4];
            float ar[4] = {a.x, a.y, a.z, a.w};
            float br[4] = {b.x, b.y, b.z, b.w};
#pragma unroll
            for (int i = 0; i < 4; i++)
#pragma unroll
                for (int j = 0; j < 4; j++)
                    acc[i][j] = fmaf(ar[i], br[j], acc[i][j]);
        }
        __syncthreads();
    }

    const int b  = row0 >> 11;
    const int m0g = (row0 & (Mm - 1)) + ty * 4;

    if (col0 < 256) {
        const bool isQ = (col0 < 128);
        const float sc = isQ ? 0.25f : 1.0f;
        __half* dst = isQ ? g_Qh : g_Kh;
        const int jcol0 = (col0 & 127) + tx * 4;     // 0..127 within Q or K
        const int h  = jcol0 >> 4;
        const int dq = jcol0 & 15;
        const float b0v = bias[jofs + tx * 4 + 0];
        const float b1v = bias[jofs + tx * 4 + 1];
        const float b2v = bias[jofs + tx * 4 + 2];
        const float b3v = bias[jofs + tx * 4 + 3];
#pragma unroll
        for (int i = 0; i < 4; i++) {
            __align__(8) __half t4[4];
            t4[0] = __float2half_rn((acc[i][0] + b0v) * sc);
            t4[1] = __float2half_rn((acc[i][1] + b1v) * sc);
            t4[2] = __float2half_rn((acc[i][2] + b2v) * sc);
            t4[3] = __float2half_rn((acc[i][3] + b3v) * sc);
            *(uint2*)&dst[(((size_t)(b * Hh + h) * Mm) + m0g + i) * 16 + dq] =
                *(uint2*)t4;
        }
    } else {
#pragma unroll
        for (int j = 0; j < 4; j++) {
            const int jcol = (col0 - 256) + tx * 4 + j;
            const int h = jcol >> 6;
            const int d = jcol & 63;
            const float bval = bias[jofs + tx * 4 + j];
            __align__(8) __half t4[4];
#pragma unroll
            for (int i = 0; i < 4; i++)
                t4[i] = __float2half_rn(acc[i][j] + bval);
            *(uint2*)&g_VTh[((size_t)(b * Hh + h) * 64 + d) * Mm + m0g] =
                *(uint2*)t4;
        }
    }
}

// ---------------------------------------------------------------------------
// Kernel 2: HMMA fp16 flash attention. 128 threads (4 warps), BM=128 rows,
// 64-key smem chunks, 16-key mma subchunks. C-frag -> A-frag P reuse.
// ---------------------------------------------------------------------------
__global__ __launch_bounds__(128) void attn_kernel(
    const int* __restrict__ mask, const float* __restrict__ gamma,
    float* __restrict__ out)
{
    __shared__ __align__(16) char Qs[128 * 48];   // q rows padded to 48B
    __shared__ __align__(16) char Ks[64 * 48];    // k rows padded to 48B
    __shared__ __align__(16) char Vs[64 * 144];   // vt rows (dv) padded to 144B
    __shared__ float mf[64];

    const int tid  = threadIdx.x;
    const int w    = tid >> 5;
    const int lane = tid & 31;
    const int g    = lane >> 2;       // row group 0..7
    const int tig  = lane & 3;        // col pair 0..3

    const int bh = blockIdx.x >> 4;
    const int mt = blockIdx.x & 15;
    const int b  = bh >> 3;
    const int h  = bh & 7;
    const int m0 = mt * 128;

    const uint32_t QsA = smem_u32(Qs);
    const uint32_t KsA = smem_u32(Ks);
    const uint32_t VsA = smem_u32(Vs);

    // load Q tile (128 rows x 16 halves) into padded smem
    {
        const uint4* q4 = (const uint4*)(g_Qh + ((size_t)bh * Mm + m0 + tid) * 16);
        *(uint4*)(Qs + tid * 48)      = q4[0];
        *(uint4*)(Qs + tid * 48 + 16) = q4[1];
    }
    __syncthreads();

    // ldmatrix lane-pattern offsets (shared by Q, K, V)
    const int rsel = (lane >> 4) & 1;   // +8 rows for mats 2,3
    const int csel = (lane >> 3) & 1;   // +16B for mats 1,3
    const int rowi = (lane & 7);

    // persistent Q A-frags: rows w*32 + mt2*16
    uint32_t qa[2][4];
#pragma unroll
    for (int mt2 = 0; mt2 < 2; mt2++) {
        // mats: (r0-7,k0-7),(r8-15,k0-7),(r0-7,k8-15),(r8-15,k8-15)
        const int qr = w * 32 + mt2 * 16 + rowi + csel * 8;   // csel: mats1,3 -> +8 rows
        const uint32_t qaddr = QsA + qr * 48 + rsel * 16;     // rsel: mats2,3 -> k8-15
        ldm4(qa[mt2], qaddr);
    }

    float o[2][8][4] = {};
    float rsum[2][2] = {};

    // per-lane ldmatrix bases for K and V (mats: (n0-7,k0-7),(n0-7,k8-15),(n8-15,k0-7),(n8-15,k8-15))
    const int knrow = rowi + rsel * 8;
    const int kcol  = csel * 16;

    for (int nt = 0; nt < 32; nt++) {
        const int n0 = nt * 64;
        __syncthreads();
        if (tid < 64) {
            const uint4* k4 = (const uint4*)(g_Kh + ((size_t)bh * Mm + n0 + tid) * 16);
            *(uint4*)(Ks + tid * 48)      = k4[0];
            *(uint4*)(Ks + tid * 48 + 16) = k4[1];
            mf[tid] = (float)mask[b * Mm + n0 + tid];
        }
        {
            const int d  = tid >> 1;
            const int ko = (tid & 1) * 32;
            const uint4* v4 = (const uint4*)(g_VTh + ((size_t)bh * 64 + d) * Mm + n0 + ko);
            char* dst = Vs + d * 144 + ko * 2;
            ((uint4*)dst)[0] = v4[0];
            ((uint4*)dst)[1] = v4[1];
            ((uint4*)dst)[2] = v4[2];
            ((uint4*)dst)[3] = v4[3];
        }
        __syncthreads();

#pragma unroll
        for (int kn = 0; kn < 4; kn++) {
            // K B-frags for 16 keys
            uint32_t kb[4];
            ldm4(kb, KsA + (kn * 16 + knrow) * 48 + kcol);

            float2 mk0 = *(float2*)&mf[kn * 16 + tig * 2];
            float2 mk1 = *(float2*)&mf[kn * 16 + 8 + tig * 2];

            uint32_t pa[2][4];
#pragma unroll
            for (int mt2 = 0; mt2 < 2; mt2++) {
                float c0[4] = {}, c1[4] = {};
                mma16816(c0, qa[mt2], kb[0], kb[1]);   // keys 0-7
                mma16816(c1, qa[mt2], kb[2], kb[3]);   // keys 8-15
                float w00 = mk0.x * __expf(fmaxf(c0[0], 0.0f));
                float w01 = mk0.y * __expf(fmaxf(c0[1], 0.0f));
                float w02 = mk0.x * __expf(fmaxf(c0[2], 0.0f));
                float w03 = mk0.y * __expf(fmaxf(c0[3], 0.0f));
                float w10 = mk1.x * __expf(fmaxf(c1[0], 0.0f));
                float w11 = mk1.y * __expf(fmaxf(c1[1], 0.0f));
                float w12 = mk1.x * __expf(fmaxf(c1[2], 0.0f));
                float w13 = mk1.y * __expf(fmaxf(c1[3], 0.0f));
                rsum[mt2][0] += (w00 + w01) + (w10 + w11);
                rsum[mt2][1] += (w02 + w03) + (w12 + w13);
                __half2 p0 = __floats2half2_rn(w00, w01);
                __half2 p1 = __floats2half2_rn(w02, w03);
                __half2 p2 = __floats2half2_rn(w10, w11);
                __half2 p3 = __floats2half2_rn(w12, w13);
                pa[mt2][0] = *(uint32_t*)&p0;   // rows g,   k 0-7
                pa[mt2][1] = *(uint32_t*)&p1;   // rows g+8, k 0-7
                pa[mt2][2] = *(uint32_t*)&p2;   // rows g,   k 8-15
                pa[mt2][3] = *(uint32_t*)&p3;   // rows g+8, k 8-15
            }

#pragma unroll
            for (int p = 0; p < 4; p++) {
                uint32_t vb[4];
                ldm4(vb, VsA + (p * 16 + knrow) * 144 + kn * 32 + kcol);
                mma16816(o[0][2 * p],     pa[0], vb[0], vb[1]);
                mma16816(o[0][2 * p + 1], pa[0], vb[2], vb[3]);
                mma16816(o[1][2 * p],     pa[1], vb[0], vb[1]);
                mma16816(o[1][2 * p + 1], pa[1], vb[2], vb[3]);
            }
        }
    }

    // row-sum reduction over the 4 lanes sharing each row
    const float gm = gamma[0];
    float inv[2][2];
#pragma unroll
    for (int mt2 = 0; mt2 < 2; mt2++)
#pragma unroll
        for (int rh = 0; rh < 2; rh++) {
            float r = rsum[mt2][rh];
            r += __shfl_xor_sync(0xFFFFFFFFu, r, 1);
            r += __shfl_xor_sync(0xFFFFFFFFu, r, 2);
            inv[mt2][rh] = gm / (r + 1e-12f);
        }

    // write O
#pragma unroll
    for (int mt2 = 0; mt2 < 2; mt2++) {
#pragma unroll
        for (int rh = 0; rh < 2; rh++) {
            const int m = m0 + w * 32 + mt2 * 16 + rh * 8 + g;
            float* op = out + ((size_t)b * Mm + m) * Cc + h * 64 + tig * 2;
            const float iv = inv[mt2][rh];
#pragma unroll
            for (int ntile = 0; ntile < 8; ntile++) {
                float2 v;
                v.x = o[mt2][ntile][rh * 2 + 0] * iv;
                v.y = o[mt2][ntile][rh * 2 + 1] * iv;
                *(float2*)(op + ntile * 8) = v;
            }
        }
    }
}

// ---------------------------------------------------------------------------
extern "C" void kernel_launch(void* const* d_in, const int* in_sizes, int n_in,
                              void* d_out, int out_size)
{
    const float* x     = (const float*)d_in[0];
    const int*   mask  = (const int*)  d_in[1];
    const float* Wq    = (const float*)d_in[2];
    const float* bq    = (const float*)d_in[3];
    const float* Wk    = (const float*)d_in[4];
    const float* bk    = (const float*)d_in[5];
    const float* Wv    = (const float*)d_in[6];
    const float* bv    = (const float*)d_in[7];
    const float* gamma = (const float*)d_in[8];
    float* out = (float*)d_out;

    dim3 pg((Bb * Mm) / 64, 12);
    proj_kernel<<<pg, 256>>>(x, Wq, bq, Wk, bk, Wv, bv);

    attn_kernel<<<BHt * (Mm / 128), 128>>>(mask, gamma, out);
}

// round 5
// speedup vs baseline: 3.8673x; 1.2676x over previous
#include <cuda_runtime.h>
#include <cuda_fp16.h>
#include <cstdint>
#include <math.h>

#define Bb 4
#define Mm 2048
#define Cc 512
#define Hh 8
#define BHt 32

// fp16 staging
__device__ __half g_xh[Bb * Mm * Cc];     // (row, k) fp16 copy of x
__device__ __half g_WT[768 * Cc];         // (j, k): Wq^T*0.25 | Wk^T | Wv^T
__device__ __half g_Qh[BHt * Mm * 16];    // (bh, m, 16)  pre-scaled by 0.25
__device__ __half g_Kh[BHt * Mm * 16];    // (bh, m, 16)
__device__ __half g_VTh[BHt * 64 * Mm];   // (bh, d, m)   transposed V

__device__ __forceinline__ uint32_t smem_u32(const void* p) {
    uint32_t a;
    asm("{ .reg .u64 t; cvta.to.shared.u64 t, %1; cvt.u32.u64 %0, t; }"
        : "=r"(a) : "l"(p));
    return a;
}
__device__ __forceinline__ void ldm4(uint32_t r[4], uint32_t addr) {
    asm volatile("ldmatrix.sync.aligned.m8n8.x4.shared.b16 {%0,%1,%2,%3}, [%4];"
                 : "=r"(r[0]), "=r"(r[1]), "=r"(r[2]), "=r"(r[3]) : "r"(addr));
}
__device__ __forceinline__ void mma16816(float c[4], const uint32_t a[4],
                                         uint32_t b0, uint32_t b1) {
    asm volatile("mma.sync.aligned.m16n8k16.row.col.f32.f16.f16.f32 "
                 "{%0,%1,%2,%3}, {%4,%5,%6,%7}, {%8,%9}, {%0,%1,%2,%3};"
                 : "+f"(c[0]), "+f"(c[1]), "+f"(c[2]), "+f"(c[3])
                 : "r"(a[0]), "r"(a[1]), "r"(a[2]), "r"(a[3]), "r"(b0), "r"(b1));
}

// ---------------------------------------------------------------------------
// Conversion kernels
// ---------------------------------------------------------------------------
__global__ void conv_x_kernel(const float* __restrict__ x)
{
    const int i = (blockIdx.x * 256 + threadIdx.x) * 4;
    float4 v = *(const float4*)&x[i];
    __align__(8) __half t[4];
    t[0] = __float2half_rn(v.x);
    t[1] = __float2half_rn(v.y);
    t[2] = __float2half_rn(v.z);
    t[3] = __float2half_rn(v.w);
    *(uint2*)&g_xh[i] = *(uint2*)t;
}

__global__ void conv_w_kernel(const float* __restrict__ Wq,
                              const float* __restrict__ Wk,
                              const float* __restrict__ Wv)
{
    const int idx = blockIdx.x * 256 + threadIdx.x;   // 768*512 total
    const int j = idx >> 9;
    const int k = idx & 511;
    float v;
    if (j < 128)      v = Wq[k * 128 + j] * 0.25f;
    else if (j < 256) v = Wk[k * 128 + (j - 128)];
    else              v = Wv[k * 512 + (j - 256)];
    g_WT[idx] = __float2half_rn(v);
}

// ---------------------------------------------------------------------------
// Kernel 1: HMMA QKV projection.  out(8192 x 768) = xh @ WT^T
// 256 threads (8 warps, 4m x 2n), CTA tile 128x128, warp tile 32x64, BK=32.
// Double-buffered smem, 80B row pitch (conflict-free ldmatrix).
// ---------------------------------------------------------------------------
__global__ __launch_bounds__(256) void proj_kernel(
    const float* __restrict__ bq, const float* __restrict__ bk,
    const float* __restrict__ bv)
{
    __shared__ __align__(16) char Ah[2][128 * 80];
    __shared__ __align__(16) char Bh[2][128 * 80];

    const int row0 = blockIdx.x * 128;
    const int col0 = blockIdx.y * 128;
    const int tid  = threadIdx.x;
    const int lane = tid & 31;
    const int wid  = tid >> 5;
    const int wm   = wid & 3;       // warp m 0..3
    const int wn   = wid >> 2;      // warp n 0..1

    const int rowi = lane & 7;
    const int rsel = (lane >> 4) & 1;
    const int csel = (lane >> 3) & 1;
    const int g    = lane >> 2;
    const int tig  = lane & 3;

    const uint32_t AhA = smem_u32(Ah);
    const uint32_t BhA = smem_u32(Bh);

    // gmem load indices: 512 uint4 per tile, 2 per thread
    const int r0 = (tid * 2) >> 2, s0 = (tid * 2) & 3;
    const int r1 = (tid * 2 + 1) >> 2, s1 = (tid * 2 + 1) & 3;

    // preload tile 0
    *(uint4*)(Ah[0] + r0 * 80 + s0 * 16) = *(const uint4*)&g_xh[(size_t)(row0 + r0) * Cc + s0 * 8];
    *(uint4*)(Ah[0] + r1 * 80 + s1 * 16) = *(const uint4*)&g_xh[(size_t)(row0 + r1) * Cc + s1 * 8];
    *(uint4*)(Bh[0] + r0 * 80 + s0 * 16) = *(const uint4*)&g_WT[(size_t)(col0 + r0) * Cc + s0 * 8];
    *(uint4*)(Bh[0] + r1 * 80 + s1 * 16) = *(const uint4*)&g_WT[(size_t)(col0 + r1) * Cc + s1 * 8];
    __syncthreads();

    float acc[2][8][4] = {};

    for (int it = 0; it < 16; it++) {
        uint4 pa0, pa1, pb0, pb1;
        if (it < 15) {
            const int kn = (it + 1) * 32;
            pa0 = *(const uint4*)&g_xh[(size_t)(row0 + r0) * Cc + kn + s0 * 8];
            pa1 = *(const uint4*)&g_xh[(size_t)(row0 + r1) * Cc + kn + s1 * 8];
            pb0 = *(const uint4*)&g_WT[(size_t)(col0 + r0) * Cc + kn + s0 * 8];
            pb1 = *(const uint4*)&g_WT[(size_t)(col0 + r1) * Cc + kn + s1 * 8];
        }
        const uint32_t Ab = AhA + (uint32_t)(it & 1) * (128 * 80);
        const uint32_t Bc = BhA + (uint32_t)(it & 1) * (128 * 80);
#pragma unroll
        for (int ks = 0; ks < 2; ks++) {
            uint32_t qa[2][4];
#pragma unroll
            for (int mt = 0; mt < 2; mt++)
                ldm4(qa[mt], Ab + (wm * 32 + mt * 16 + rowi + csel * 8) * 80
                              + ks * 32 + rsel * 16);
#pragma unroll
            for (int nb = 0; nb < 4; nb++) {
                uint32_t kb[4];
                ldm4(kb, Bc + (wn * 64 + nb * 16 + rowi + rsel * 8) * 80
                           + ks * 32 + csel * 16);
                mma16816(acc[0][nb * 2],     qa[0], kb[0], kb[1]);
                mma16816(acc[0][nb * 2 + 1], qa[0], kb[2], kb[3]);
                mma16816(acc[1][nb * 2],     qa[1], kb[0], kb[1]);
                mma16816(acc[1][nb * 2 + 1], qa[1], kb[2], kb[3]);
            }
        }
        if (it < 15) {
            char* An = Ah[(it + 1) & 1];
            char* Bn = Bh[(it + 1) & 1];
            *(uint4*)(An + r0 * 80 + s0 * 16) = pa0;
            *(uint4*)(An + r1 * 80 + s1 * 16) = pa1;
            *(uint4*)(Bn + r0 * 80 + s0 * 16) = pb0;
            *(uint4*)(Bn + r1 * 80 + s1 * 16) = pb1;
            __syncthreads();
        }
    }

    // epilogue
    const int b   = row0 >> 11;
    const int mloc = (row0 & (Mm - 1)) + wm * 32;

#pragma unroll
    for (int mt = 0; mt < 2; mt++) {
        const int ma = mloc + mt * 16 + g;
#pragma unroll
        for (int j = 0; j < 8; j++) {
            const int jg = col0 + wn * 64 + j * 8 + tig * 2;
            float c0 = acc[mt][j][0], c1 = acc[mt][j][1];
            float c2 = acc[mt][j][2], c3 = acc[mt][j][3];
            if (jg < 128) {
                const float b0 = bq[jg] * 0.25f, b1 = bq[jg + 1] * 0.25f;
                const int h = jg >> 4, dq = jg & 15;
                __half2 lo = __floats2half2_rn(c0 + b0, c1 + b1);
                __half2 hi = __floats2half2_rn(c2 + b0, c3 + b1);
                __half* base = &g_Qh[(((size_t)(b * Hh + h)) * Mm + ma) * 16 + dq];
                *(uint32_t*)base = *(uint32_t*)&lo;
                *(uint32_t*)(base + 8 * 16) = *(uint32_t*)&hi;
            } else if (jg < 256) {
                const int jj = jg - 128;
                const float b0 = bk[jj], b1 = bk[jj + 1];
                const int h = jj >> 4, dq = jj & 15;
                __half2 lo = __floats2half2_rn(c0 + b0, c1 + b1);
                __half2 hi = __floats2half2_rn(c2 + b0, c3 + b1);
                __half* base = &g_Kh[(((size_t)(b * Hh + h)) * Mm + ma) * 16 + dq];
                *(uint32_t*)base = *(uint32_t*)&lo;
                *(uint32_t*)(base + 8 * 16) = *(uint32_t*)&hi;
            } else {
                const int jj = jg - 256;
                const float b0 = bv[jj], b1 = bv[jj + 1];
                const int h = jj >> 6, d = jj & 63;
                __half* base = &g_VTh[(((size_t)(b * Hh + h)) * 64 + d) * Mm + ma];
                base[0]            = __float2half_rn(c0 + b0);
                base[Mm]           = __float2half_rn(c1 + b1);
                base[8]            = __float2half_rn(c2 + b0);
                base[Mm + 8]       = __float2half_rn(c3 + b1);
            }
        }
    }
}

// ---------------------------------------------------------------------------
// Kernel 2: HMMA fp16 flash attention (unchanged from R4, passed @92us).
// ---------------------------------------------------------------------------
__global__ __launch_bounds__(128) void attn_kernel(
    const int* __restrict__ mask, const float* __restrict__ gamma,
    float* __restrict__ out)
{
    __shared__ __align__(16) char Qs[128 * 48];
    __shared__ __align__(16) char Ks[64 * 48];
    __shared__ __align__(16) char Vs[64 * 144];
    __shared__ float mf[64];

    const int tid  = threadIdx.x;
    const int w    = tid >> 5;
    const int lane = tid & 31;
    const int g    = lane >> 2;
    const int tig  = lane & 3;

    const int bh = blockIdx.x >> 4;
    const int mt = blockIdx.x & 15;
    const int b  = bh >> 3;
    const int h  = bh & 7;
    const int m0 = mt * 128;

    const uint32_t QsA = smem_u32(Qs);
    const uint32_t KsA = smem_u32(Ks);
    const uint32_t VsA = smem_u32(Vs);

    {
        const uint4* q4 = (const uint4*)(g_Qh + ((size_t)bh * Mm + m0 + tid) * 16);
        *(uint4*)(Qs + tid * 48)      = q4[0];
        *(uint4*)(Qs + tid * 48 + 16) = q4[1];
    }
    __syncthreads();

    const int rsel = (lane >> 4) & 1;
    const int csel = (lane >> 3) & 1;
    const int rowi = (lane & 7);

    uint32_t qa[2][4];
#pragma unroll
    for (int mt2 = 0; mt2 < 2; mt2++) {
        const int qr = w * 32 + mt2 * 16 + rowi + csel * 8;
        const uint32_t qaddr = QsA + qr * 48 + rsel * 16;
        ldm4(qa[mt2], qaddr);
    }

    float o[2][8][4] = {};
    float rsum[2][2] = {};

    const int knrow = rowi + rsel * 8;
    const int kcol  = csel * 16;

    for (int nt = 0; nt < 32; nt++) {
        const int n0 = nt * 64;
        __syncthreads();
        if (tid < 64) {
            const uint4* k4 = (const uint4*)(g_Kh + ((size_t)bh * Mm + n0 + tid) * 16);
            *(uint4*)(Ks + tid * 48)      = k4[0];
            *(uint4*)(Ks + tid * 48 + 16) = k4[1];
            mf[tid] = (float)mask[b * Mm + n0 + tid];
        }
        {
            const int d  = tid >> 1;
            const int ko = (tid & 1) * 32;
            const uint4* v4 = (const uint4*)(g_VTh + ((size_t)bh * 64 + d) * Mm + n0 + ko);
            char* dst = Vs + d * 144 + ko * 2;
            ((uint4*)dst)[0] = v4[0];
            ((uint4*)dst)[1] = v4[1];
            ((uint4*)dst)[2] = v4[2];
            ((uint4*)dst)[3] = v4[3];
        }
        __syncthreads();

#pragma unroll
        for (int kn = 0; kn < 4; kn++) {
            uint32_t kb[4];
            ldm4(kb, KsA + (kn * 16 + knrow) * 48 + kcol);

            float2 mk0 = *(float2*)&mf[kn * 16 + tig * 2];
            float2 mk1 = *(float2*)&mf[kn * 16 + 8 + tig * 2];

            uint32_t pa[2][4];
#pragma unroll
            for (int mt2 = 0; mt2 < 2; mt2++) {
                float c0[4] = {}, c1[4] = {};
                mma16816(c0, qa[mt2], kb[0], kb[1]);
                mma16816(c1, qa[mt2], kb[2], kb[3]);
                float w00 = mk0.x * __expf(fmaxf(c0[0], 0.0f));
                float w01 = mk0.y * __expf(fmaxf(c0[1], 0.0f));
                float w02 = mk0.x * __expf(fmaxf(c0[2], 0.0f));
                float w03 = mk0.y * __expf(fmaxf(c0[3], 0.0f));
                float w10 = mk1.x * __expf(fmaxf(c1[0], 0.0f));
                float w11 = mk1.y * __expf(fmaxf(c1[1], 0.0f));
                float w12 = mk1.x * __expf(fmaxf(c1[2], 0.0f));
                float w13 = mk1.y * __expf(fmaxf(c1[3], 0.0f));
                rsum[mt2][0] += (w00 + w01) + (w10 + w11);
                rsum[mt2][1] += (w02 + w03) + (w12 + w13);
                __half2 p0 = __floats2half2_rn(w00, w01);
                __half2 p1 = __floats2half2_rn(w02, w03);
                __half2 p2 = __floats2half2_rn(w10, w11);
                __half2 p3 = __floats2half2_rn(w12, w13);
                pa[mt2][0] = *(uint32_t*)&p0;
                pa[mt2][1] = *(uint32_t*)&p1;
                pa[mt2][2] = *(uint32_t*)&p2;
                pa[mt2][3] = *(uint32_t*)&p3;
            }

#pragma unroll
            for (int p = 0; p < 4; p++) {
                uint32_t vb[4];
                ldm4(vb, VsA + (p * 16 + knrow) * 144 + kn * 32 + kcol);
                mma16816(o[0][2 * p],     pa[0], vb[0], vb[1]);
                mma16816(o[0][2 * p + 1], pa[0], vb[2], vb[3]);
                mma16816(o[1][2 * p],     pa[1], vb[0], vb[1]);
                mma16816(o[1][2 * p + 1], pa[1], vb[2], vb[3]);
            }
        }
    }

    const float gm = gamma[0];
    float inv[2][2];
#pragma unroll
    for (int mt2 = 0; mt2 < 2; mt2++)
#pragma unroll
        for (int rh = 0; rh < 2; rh++) {
            float r = rsum[mt2][rh];
            r += __shfl_xor_sync(0xFFFFFFFFu, r, 1);
            r += __shfl_xor_sync(0xFFFFFFFFu, r, 2);
            inv[mt2][rh] = gm / (r + 1e-12f);
        }

#pragma unroll
    for (int mt2 = 0; mt2 < 2; mt2++) {
#pragma unroll
        for (int rh = 0; rh < 2; rh++) {
            const int m = m0 + w * 32 + mt2 * 16 + rh * 8 + g;
            float* op = out + ((size_t)b * Mm + m) * Cc + h * 64 + tig * 2;
            const float iv = inv[mt2][rh];
#pragma unroll
            for (int ntile = 0; ntile < 8; ntile++) {
                float2 v;
                v.x = o[mt2][ntile][rh * 2 + 0] * iv;
                v.y = o[mt2][ntile][rh * 2 + 1] * iv;
                *(float2*)(op + ntile * 8) = v;
            }
        }
    }
}

// ---------------------------------------------------------------------------
extern "C" void kernel_launch(void* const* d_in, const int* in_sizes, int n_in,
                              void* d_out, int out_size)
{
    const float* x     = (const float*)d_in[0];
    const int*   mask  = (const int*)  d_in[1];
    const float* Wq    = (const float*)d_in[2];
    const float* bq    = (const float*)d_in[3];
    const float* Wk    = (const float*)d_in[4];
    const float* bk    = (const float*)d_in[5];
    const float* Wv    = (const float*)d_in[6];
    const float* bv    = (const float*)d_in[7];
    const float* gamma = (const float*)d_in[8];
    float* out = (float*)d_out;

    conv_x_kernel<<<(Bb * Mm * Cc) / (256 * 4), 256>>>(x);
    conv_w_kernel<<<(768 * Cc) / 256, 256>>>(Wq, Wk, Wv);

    dim3 pg((Bb * Mm) / 128, 6);
    proj_kernel<<<pg, 256>>>(bq, bk, bv);

    attn_kernel<<<BHt * (Mm / 128), 128>>>(mask, gamma, out);
}

// round 9
// speedup vs baseline: 6.2372x; 1.6128x over previous
#include <cuda_runtime.h>
#include <cuda_fp16.h>
#include <cstdint>
#include <math.h>

#define Bb 4
#define Mm 2048
#define Cc 512
#define Hh 8
#define BHt 32

#define QSCALE 0.36067376022224085f   // 0.25 * log2(e)

// fp16 staging
__device__ __half g_WT[768 * Cc];         // (j, k): Wq^T*QSCALE | Wk^T | Wv^T
__device__ __half g_Qh[BHt * Mm * 16];    // (bh, m, 16)  pre-scaled by QSCALE
__device__ __half g_Kh[BHt * Mm * 16];    // (bh, m, 16)
__device__ __half g_VTh[BHt * 64 * Mm];   // (bh, d, m)   transposed V

__device__ __forceinline__ uint32_t smem_u32(const void* p) {
    uint32_t a;
    asm("{ .reg .u64 t; cvta.to.shared.u64 t, %1; cvt.u32.u64 %0, t; }"
        : "=r"(a) : "l"(p));
    return a;
}
__device__ __forceinline__ void ldm4(uint32_t r[4], uint32_t addr) {
    asm volatile("ldmatrix.sync.aligned.m8n8.x4.shared.b16 {%0,%1,%2,%3}, [%4];"
                 : "=r"(r[0]), "=r"(r[1]), "=r"(r[2]), "=r"(r[3]) : "r"(addr));
}
__device__ __forceinline__ void mma16816(float c[4], const uint32_t a[4],
                                         uint32_t b0, uint32_t b1) {
    asm volatile("mma.sync.aligned.m16n8k16.row.col.f32.f16.f16.f32 "
                 "{%0,%1,%2,%3}, {%4,%5,%6,%7}, {%8,%9}, {%0,%1,%2,%3};"
                 : "+f"(c[0]), "+f"(c[1]), "+f"(c[2]), "+f"(c[3])
                 : "r"(a[0]), "r"(a[1]), "r"(a[2]), "r"(a[3]), "r"(b0), "r"(b1));
}
__device__ __forceinline__ float ex2f(float x) {
    float y;
    asm("ex2.approx.f32 %0, %1;" : "=f"(y) : "f"(x));
    return y;
}
#define CP16(dst, src) \
    asm volatile("cp.async.ca.shared.global [%0], [%1], 16;" :: "r"(dst), "l"(src))
#define CP_COMMIT() asm volatile("cp.async.commit_group;")
#define CP_WAIT1()  asm volatile("cp.async.wait_group 1;")
#define CP_WAIT0()  asm volatile("cp.async.wait_group 0;")

__device__ __forceinline__ uint4 f8_to_h8(float4 a, float4 b) {
    __half2 h0 = __floats2half2_rn(a.x, a.y), h1 = __floats2half2_rn(a.z, a.w);
    __half2 h2 = __floats2half2_rn(b.x, b.y), h3 = __floats2half2_rn(b.z, b.w);
    uint4 u;
    u.x = *(uint32_t*)&h0; u.y = *(uint32_t*)&h1;
    u.z = *(uint32_t*)&h2; u.w = *(uint32_t*)&h3;
    return u;
}

// ---------------------------------------------------------------------------
// Weight conversion (fp32 -> fp16 transposed; Wq gets QSCALE folded in)
// ---------------------------------------------------------------------------
__global__ void conv_w_kernel(const float* __restrict__ Wq,
                              const float* __restrict__ Wk,
                              const float* __restrict__ Wv)
{
    const int idx = blockIdx.x * 256 + threadIdx.x;   // 768*512 total
    const int j = idx >> 9;
    const int k = idx & 511;
    float v;
    if (j < 128)      v = Wq[k * 128 + j] * QSCALE;
    else if (j < 256) v = Wk[k * 128 + (j - 128)];
    else              v = Wv[k * 512 + (j - 256)];
    g_WT[idx] = __float2half_rn(v);
}

// ---------------------------------------------------------------------------
// Kernel 1: HMMA QKV projection, fp32 x loaded + converted in-register.
// 256 threads (8 warps, 4m x 2n), CTA tile 128x128, warp tile 32x64, BK=32.
// ---------------------------------------------------------------------------
__global__ __launch_bounds__(256) void proj_kernel(
    const float* __restrict__ x,
    const float* __restrict__ bq, const float* __restrict__ bk,
    const float* __restrict__ bv)
{
    __shared__ __align__(16) char Ah[2][128 * 80];
    __shared__ __align__(16) char Bh[2][128 * 80];

    const int row0 = blockIdx.x * 128;
    const int col0 = blockIdx.y * 128;
    const int tid  = threadIdx.x;
    const int lane = tid & 31;
    const int wid  = tid >> 5;
    const int wm   = wid & 3;
    const int wn   = wid >> 2;

    const int rowi = lane & 7;
    const int rsel = (lane >> 4) & 1;
    const int csel = (lane >> 3) & 1;
    const int g    = lane >> 2;
    const int tig  = lane & 3;

    const uint32_t AhA = smem_u32(Ah);
    const uint32_t BhA = smem_u32(Bh);

    const int r0 = (tid * 2) >> 2, s0 = (tid * 2) & 3;
    const int r1 = (tid * 2 + 1) >> 2, s1 = (tid * 2 + 1) & 3;

    const float* xa0 = x + (size_t)(row0 + r0) * Cc + s0 * 8;
    const float* xa1 = x + (size_t)(row0 + r1) * Cc + s1 * 8;
    const __half* wb0 = g_WT + (size_t)(col0 + r0) * Cc + s0 * 8;
    const __half* wb1 = g_WT + (size_t)(col0 + r1) * Cc + s1 * 8;

    // preload tile 0
    {
        float4 a00 = *(const float4*)xa0, a01 = *(const float4*)(xa0 + 4);
        float4 a10 = *(const float4*)xa1, a11 = *(const float4*)(xa1 + 4);
        *(uint4*)(Ah[0] + r0 * 80 + s0 * 16) = f8_to_h8(a00, a01);
        *(uint4*)(Ah[0] + r1 * 80 + s1 * 16) = f8_to_h8(a10, a11);
        *(uint4*)(Bh[0] + r0 * 80 + s0 * 16) = *(const uint4*)wb0;
        *(uint4*)(Bh[0] + r1 * 80 + s1 * 16) = *(const uint4*)wb1;
    }
    __syncthreads();

    float acc[2][8][4] = {};

    for (int it = 0; it < 16; it++) {
        float4 a00, a01, a10, a11;
        uint4 pb0, pb1;
        if (it < 15) {
            const int kn = (it + 1) * 32;
            a00 = *(const float4*)(xa0 + kn);
            a01 = *(const float4*)(xa0 + kn + 4);
            a10 = *(const float4*)(xa1 + kn);
            a11 = *(const float4*)(xa1 + kn + 4);
            pb0 = *(const uint4*)(wb0 + kn);
            pb1 = *(const uint4*)(wb1 + kn);
        }
        const uint32_t Ab = AhA + (uint32_t)(it & 1) * (128 * 80);
        const uint32_t Bc = BhA + (uint32_t)(it & 1) * (128 * 80);
#pragma unroll
        for (int ks = 0; ks < 2; ks++) {
            uint32_t qa[2][4];
#pragma unroll
            for (int mt = 0; mt < 2; mt++)
                ldm4(qa[mt], Ab + (wm * 32 + mt * 16 + rowi + csel * 8) * 80
                              + ks * 32 + rsel * 16);
#pragma unroll
            for (int nb = 0; nb < 4; nb++) {
                uint32_t kb[4];
                ldm4(kb, Bc + (wn * 64 + nb * 16 + rowi + rsel * 8) * 80
                           + ks * 32 + csel * 16);
                mma16816(acc[0][nb * 2],     qa[0], kb[0], kb[1]);
                mma16816(acc[0][nb * 2 + 1], qa[0], kb[2], kb[3]);
                mma16816(acc[1][nb * 2],     qa[1], kb[0], kb[1]);
                mma16816(acc[1][nb * 2 + 1], qa[1], kb[2], kb[3]);
            }
        }
        if (it < 15) {
            char* An = Ah[(it + 1) & 1];
            char* Bn = Bh[(it + 1) & 1];
            *(uint4*)(An + r0 * 80 + s0 * 16) = f8_to_h8(a00, a01);
            *(uint4*)(An + r1 * 80 + s1 * 16) = f8_to_h8(a10, a11);
            *(uint4*)(Bn + r0 * 80 + s0 * 16) = pb0;
            *(uint4*)(Bn + r1 * 80 + s1 * 16) = pb1;
            __syncthreads();
        }
    }

    // epilogue
    const int b    = row0 >> 11;
    const int mloc = (row0 & (Mm - 1)) + wm * 32;

#pragma unroll
    for (int mt = 0; mt < 2; mt++) {
        const int ma = mloc + mt * 16 + g;
#pragma unroll
        for (int j = 0; j < 8; j++) {
            const int jg = col0 + wn * 64 + j * 8 + tig * 2;
            float c0 = acc[mt][j][0], c1 = acc[mt][j][1];
            float c2 = acc[mt][j][2], c3 = acc[mt][j][3];
            if (jg < 128) {
                const float b0 = bq[jg] * QSCALE, b1 = bq[jg + 1] * QSCALE;
                const int h = jg >> 4, dq = jg & 15;
                __half2 lo = __floats2half2_rn(c0 + b0, c1 + b1);
                __half2 hi = __floats2half2_rn(c2 + b0, c3 + b1);
                __half* base = &g_Qh[(((size_t)(b * Hh + h)) * Mm + ma) * 16 + dq];
                *(uint32_t*)base = *(uint32_t*)&lo;
                *(uint32_t*)(base + 8 * 16) = *(uint32_t*)&hi;
            } else if (jg < 256) {
                const int jj = jg - 128;
                const float b0 = bk[jj], b1 = bk[jj + 1];
                const int h = jj >> 4, dq = jj & 15;
                __half2 lo = __floats2half2_rn(c0 + b0, c1 + b1);
                __half2 hi = __floats2half2_rn(c2 + b0, c3 + b1);
                __half* base = &g_Kh[(((size_t)(b * Hh + h)) * Mm + ma) * 16 + dq];
                *(uint32_t*)base = *(uint32_t*)&lo;
                *(uint32_t*)(base + 8 * 16) = *(uint32_t*)&hi;
            } else {
                const int jj = jg - 256;
                const float b0 = bv[jj], b1 = bv[jj + 1];
                const int h = jj >> 6, d = jj & 63;
                __half* base = &g_VTh[(((size_t)(b * Hh + h)) * 64 + d) * Mm + ma];
                base[0]      = __float2half_rn(c0 + b0);
                base[Mm]     = __float2half_rn(c1 + b1);
                base[8]      = __float2half_rn(c2 + b0);
                base[Mm + 8] = __float2half_rn(c3 + b1);
            }
        }
    }
}

// ---------------------------------------------------------------------------
// Kernel 2: HMMA fp16 flash attention with cp.async double-buffered K/V/mask.
// w = mask * ex2(relu(s)) with log2e pre-folded into Q.
// ---------------------------------------------------------------------------
#define KB 3072
#define VB 9216

__global__ __launch_bounds__(128, 4) void attn_kernel(
    const int* __restrict__ mask, const float* __restrict__ gamma,
    float* __restrict__ out)
{
    __shared__ __align__(16) char Qs[128 * 48];
    __shared__ __align__(16) char Ks[2][64 * 48];
    __shared__ __align__(16) char Vs[2][64 * 144];
    __shared__ __align__(16) int  Ms[2][64];

    const int tid  = threadIdx.x;
    const int w    = tid >> 5;
    const int lane = tid & 31;
    const int g    = lane >> 2;
    const int tig  = lane & 3;

    const int bh = blockIdx.x >> 4;
    const int mt = blockIdx.x & 15;
    const int b  = bh >> 3;
    const int h  = bh & 7;
    const int m0 = mt * 128;

    const uint32_t QsA = smem_u32(Qs);
    const uint32_t KsA = smem_u32(Ks);
    const uint32_t VsA = smem_u32(Vs);
    const uint32_t MsA = smem_u32(Ms);

    {
        const uint4* q4 = (const uint4*)(g_Qh + ((size_t)bh * Mm + m0 + tid) * 16);
        *(uint4*)(Qs + tid * 48)      = q4[0];
        *(uint4*)(Qs + tid * 48 + 16) = q4[1];
    }

    // async tile issue: all threads V (4x16B), tid<64 K (2x16B), tid<16 mask
    const __half* vsrc0 = g_VTh + ((size_t)bh * 64 + (tid >> 1)) * Mm + (tid & 1) * 32;
    const uint32_t vdst0 = VsA + (uint32_t)((tid >> 1) * 144 + (tid & 1) * 64);
    const __half* ksrc0 = g_Kh + ((size_t)bh * Mm + tid) * 16;
    const uint32_t kdst0 = KsA + (uint32_t)(tid * 48);
    const int* msrc0 = mask + b * Mm + tid * 4;
    const uint32_t mdst0 = MsA + (uint32_t)(tid * 16);

    auto issue_tile = [&](int nt, int buf) {
        const int n0 = nt * 64;
        const __half* vs = vsrc0 + n0;
        const uint32_t vd = vdst0 + (uint32_t)buf * VB;
        CP16(vd,      vs);
        CP16(vd + 16, vs + 8);
        CP16(vd + 32, vs + 16);
        CP16(vd + 48, vs + 24);
        if (tid < 64) {
            const __half* ks = ksrc0 + (size_t)n0 * 16;
            const uint32_t kd = kdst0 + (uint32_t)buf * KB;
            CP16(kd,      ks);
            CP16(kd + 16, ks + 8);
        }
        if (tid < 16) CP16(mdst0 + (uint32_t)buf * 256, msrc0 + n0);
    };

    issue_tile(0, 0);
    CP_COMMIT();
    __syncthreads();   // Qs visible

    const int rsel = (lane >> 4) & 1;
    const int csel = (lane >> 3) & 1;
    const int rowi = (lane & 7);

    uint32_t qa[2][4];
#pragma unroll
    for (int mt2 = 0; mt2 < 2; mt2++)
        ldm4(qa[mt2], QsA + (w * 32 + mt2 * 16 + rowi + csel * 8) * 48 + rsel * 16);

    float o[2][8][4] = {};
    float rsum[2][2] = {};

    const int knrow = rowi + rsel * 8;
    const int kcol  = csel * 16;

    for (int nt = 0; nt < 32; nt++) {
        const int buf = nt & 1;
        if (nt + 1 < 32) {
            issue_tile(nt + 1, buf ^ 1);
            CP_COMMIT();
            CP_WAIT1();
        } else {
            CP_WAIT0();
        }
        __syncthreads();

        const uint32_t Kb = KsA + (uint32_t)buf * KB;
        const uint32_t Vb = VsA + (uint32_t)buf * VB;
        const int* mi = Ms[buf];

#pragma unroll
        for (int kn = 0; kn < 4; kn++) {
            uint32_t kb[4];
            ldm4(kb, Kb + (kn * 16 + knrow) * 48 + kcol);

            const float mk0x = (float)mi[kn * 16 + tig * 2];
            const float mk0y = (float)mi[kn * 16 + tig * 2 + 1];
            const float mk1x = (float)mi[kn * 16 + 8 + tig * 2];
            const float mk1y = (float)mi[kn * 16 + 8 + tig * 2 + 1];

            uint32_t pa[2][4];
#pragma unroll
            for (int mt2 = 0; mt2 < 2; mt2++) {
                float c0[4] = {}, c1[4] = {};
                mma16816(c0, qa[mt2], kb[0], kb[1]);
                mma16816(c1, qa[mt2], kb[2], kb[3]);
                float w00 = mk0x * ex2f(fmaxf(c0[0], 0.0f));
                float w01 = mk0y * ex2f(fmaxf(c0[1], 0.0f));
                float w02 = mk0x * ex2f(fmaxf(c0[2], 0.0f));
                float w03 = mk0y * ex2f(fmaxf(c0[3], 0.0f));
                float w10 = mk1x * ex2f(fmaxf(c1[0], 0.0f));
                float w11 = mk1y * ex2f(fmaxf(c1[1], 0.0f));
                float w12 = mk1x * ex2f(fmaxf(c1[2], 0.0f));
                float w13 = mk1y * ex2f(fmaxf(c1[3], 0.0f));
                rsum[mt2][0] += (w00 + w01) + (w10 + w11);
                rsum[mt2][1] += (w02 + w03) + (w12 + w13);
                __half2 p0 = __floats2half2_rn(w00, w01);
                __half2 p1 = __floats2half2_rn(w02, w03);
                __half2 p2 = __floats2half2_rn(w10, w11);
                __half2 p3 = __floats2half2_rn(w12, w13);
                pa[mt2][0] = *(uint32_t*)&p0;
                pa[mt2][1] = *(uint32_t*)&p1;
                pa[mt2][2] = *(uint32_t*)&p2;
                pa[mt2][3] = *(uint32_t*)&p3;
            }

#pragma unroll
            for (int p = 0; p < 4; p++) {
                uint32_t vb[4];
                ldm4(vb, Vb + (p * 16 + knrow) * 144 + kn * 32 + kcol);
                mma16816(o[0][2 * p],     pa[0], vb[0], vb[1]);
                mma16816(o[0][2 * p + 1], pa[0], vb[2], vb[3]);
                mma16816(o[1][2 * p],     pa[1], vb[0], vb[1]);
                mma16816(o[1][2 * p + 1], pa[1], vb[2], vb[3]);
            }
        }
        __syncthreads();
    }

    const float gm = gamma[0];
    float inv[2][2];
#pragma unroll
    for (int mt2 = 0; mt2 < 2; mt2++)
#pragma unroll
        for (int rh = 0; rh < 2; rh++) {
            float r = rsum[mt2][rh];
            r += __shfl_xor_sync(0xFFFFFFFFu, r, 1);
            r += __shfl_xor_sync(0xFFFFFFFFu, r, 2);
            inv[mt2][rh] = gm / (r + 1e-12f);
        }

#pragma unroll
    for (int mt2 = 0; mt2 < 2; mt2++) {
#pragma unroll
        for (int rh = 0; rh < 2; rh++) {
            const int m = m0 + w * 32 + mt2 * 16 + rh * 8 + g;
            float* op = out + ((size_t)b * Mm + m) * Cc + h * 64 + tig * 2;
            const float iv = inv[mt2][rh];
#pragma unroll
            for (int ntile = 0; ntile < 8; ntile++) {
                float2 v;
                v.x = o[mt2][ntile][rh * 2 + 0] * iv;
                v.y = o[mt2][ntile][rh * 2 + 1] * iv;
                *(float2*)(op + ntile * 8) = v;
            }
        }
    }
}

// ---------------------------------------------------------------------------
extern "C" void kernel_launch(void* const* d_in, const int* in_sizes, int n_in,
                              void* d_out, int out_size)
{
    const float* x     = (const float*)d_in[0];
    const int*   mask  = (const int*)  d_in[1];
    const float* Wq    = (const float*)d_in[2];
    const float* bq    = (const float*)d_in[3];
    const float* Wk    = (const float*)d_in[4];
    const float* bk    = (const float*)d_in[5];
    const float* Wv    = (const float*)d_in[6];
    const float* bv    = (const float*)d_in[7];
    const float* gamma = (const float*)d_in[8];
    float* out = (float*)d_out;

    conv_w_kernel<<<(768 * Cc) / 256, 256>>>(Wq, Wk, Wv);

    dim3 pg((Bb * Mm) / 128, 6);
    proj_kernel<<<pg, 256>>>(x, bq, bk, bv);

    attn_kernel<<<BHt * (Mm / 128), 128>>>(mask, gamma, out);
}

// round 10
// speedup vs baseline: 7.0605x; 1.1320x over previous
#include <cuda_runtime.h>
#include <cuda_fp16.h>
#include <cstdint>
#include <math.h>

#define Bb 4
#define Mm 2048
#define Cc 512
#define Hh 8
#define BHt 32
#define VTR 72                         // VT rows per bh: 64 V + 1 mask + 7 zero pad

#define QSCALE 0.36067376022224085f    // 0.25 * log2(e)

// fp16 staging
__device__ __half g_WT[768 * Cc];          // (j, k): Wq^T*QSCALE | Wk^T | Wv^T
__device__ __half g_Qh[BHt * Mm * 16];     // (bh, m, 16)  pre-scaled by QSCALE
__device__ __half g_Kh[BHt * Mm * 16];     // (bh, m, 16)
__device__ __half g_VTh[BHt * VTR * Mm];   // (bh, d, m); d=64 mask row; 65-71 zero

__device__ __forceinline__ uint32_t smem_u32(const void* p) {
    uint32_t a;
    asm("{ .reg .u64 t; cvta.to.shared.u64 t, %1; cvt.u32.u64 %0, t; }"
        : "=r"(a) : "l"(p));
    return a;
}
__device__ __forceinline__ void ldm4(uint32_t r[4], uint32_t addr) {
    asm volatile("ldmatrix.sync.aligned.m8n8.x4.shared.b16 {%0,%1,%2,%3}, [%4];"
                 : "=r"(r[0]), "=r"(r[1]), "=r"(r[2]), "=r"(r[3]) : "r"(addr));
}
__device__ __forceinline__ void ldm2(uint32_t r[2], uint32_t addr) {
    asm volatile("ldmatrix.sync.aligned.m8n8.x2.shared.b16 {%0,%1}, [%2];"
                 : "=r"(r[0]), "=r"(r[1]) : "r"(addr));
}
__device__ __forceinline__ void mma16816(float c[4], const uint32_t a[4],
                                         uint32_t b0, uint32_t b1) {
    asm volatile("mma.sync.aligned.m16n8k16.row.col.f32.f16.f16.f32 "
                 "{%0,%1,%2,%3}, {%4,%5,%6,%7}, {%8,%9}, {%0,%1,%2,%3};"
                 : "+f"(c[0]), "+f"(c[1]), "+f"(c[2]), "+f"(c[3])
                 : "r"(a[0]), "r"(a[1]), "r"(a[2]), "r"(a[3]), "r"(b0), "r"(b1));
}
// P = ex2(relu(.)) on a packed pair; returns half2 as uint32
__device__ __forceinline__ uint32_t exp_relu_pack(float lo, float hi) {
    uint32_t h, r;
    asm("cvt.rn.f16x2.f32 %0, %1, %2;" : "=r"(h) : "f"(hi), "f"(lo));
    asm("max.f16x2 %0, %0, %1;" : "+r"(h) : "r"(0u));
    asm("ex2.approx.f16x2 %0, %1;" : "=r"(r) : "r"(h));
    return r;
}
#define CP16(dst, src) \
    asm volatile("cp.async.ca.shared.global [%0], [%1], 16;" :: "r"(dst), "l"(src))
#define CP_COMMIT() asm volatile("cp.async.commit_group;")
#define CP_WAIT1()  asm volatile("cp.async.wait_group 1;")
#define CP_WAIT0()  asm volatile("cp.async.wait_group 0;")

__device__ __forceinline__ uint4 f8_to_h8(float4 a, float4 b) {
    __half2 h0 = __floats2half2_rn(a.x, a.y), h1 = __floats2half2_rn(a.z, a.w);
    __half2 h2 = __floats2half2_rn(b.x, b.y), h3 = __floats2half2_rn(b.z, b.w);
    uint4 u;
    u.x = *(uint32_t*)&h0; u.y = *(uint32_t*)&h1;
    u.z = *(uint32_t*)&h2; u.w = *(uint32_t*)&h3;
    return u;
}

// ---------------------------------------------------------------------------
// Weight conversion + VT mask row fill
// ---------------------------------------------------------------------------
__global__ void conv_w_kernel(const float* __restrict__ Wq,
                              const float* __restrict__ Wk,
                              const float* __restrict__ Wv,
                              const int* __restrict__ mask)
{
    const int idx = blockIdx.x * 256 + threadIdx.x;
    if (idx < 768 * Cc) {
        const int j = idx >> 9;
        const int k = idx & 511;
        float v;
        if (j < 128)      v = Wq[k * 128 + j] * QSCALE;
        else if (j < 256) v = Wk[k * 128 + (j - 128)];
        else              v = Wv[k * 512 + (j - 256)];
        g_WT[idx] = __float2half_rn(v);
    } else {
        const int i2 = idx - 768 * Cc;          // 0..65535
        const int bh = i2 >> 11;
        const int m  = i2 & 2047;
        g_VTh[((size_t)bh * VTR + 64) * Mm + m] =
            __float2half_rn((float)mask[(bh >> 3) * Mm + m]);
    }
}

// ---------------------------------------------------------------------------
// Kernel 1: HMMA QKV projection; V rows get mask folded in at write time.
// ---------------------------------------------------------------------------
__global__ __launch_bounds__(256) void proj_kernel(
    const float* __restrict__ x, const int* __restrict__ mask,
    const float* __restrict__ bq, const float* __restrict__ bk,
    const float* __restrict__ bv)
{
    __shared__ __align__(16) char Ah[2][128 * 80];
    __shared__ __align__(16) char Bh[2][128 * 80];

    const int row0 = blockIdx.x * 128;
    const int col0 = blockIdx.y * 128;
    const int tid  = threadIdx.x;
    const int lane = tid & 31;
    const int wid  = tid >> 5;
    const int wm   = wid & 3;
    const int wn   = wid >> 2;

    const int rowi = lane & 7;
    const int rsel = (lane >> 4) & 1;
    const int csel = (lane >> 3) & 1;
    const int g    = lane >> 2;
    const int tig  = lane & 3;

    const uint32_t AhA = smem_u32(Ah);
    const uint32_t BhA = smem_u32(Bh);

    const int r0 = (tid * 2) >> 2, s0 = (tid * 2) & 3;
    const int r1 = (tid * 2 + 1) >> 2, s1 = (tid * 2 + 1) & 3;

    const float* xa0 = x + (size_t)(row0 + r0) * Cc + s0 * 8;
    const float* xa1 = x + (size_t)(row0 + r1) * Cc + s1 * 8;
    const __half* wb0 = g_WT + (size_t)(col0 + r0) * Cc + s0 * 8;
    const __half* wb1 = g_WT + (size_t)(col0 + r1) * Cc + s1 * 8;

    {
        float4 a00 = *(const float4*)xa0, a01 = *(const float4*)(xa0 + 4);
        float4 a10 = *(const float4*)xa1, a11 = *(const float4*)(xa1 + 4);
        *(uint4*)(Ah[0] + r0 * 80 + s0 * 16) = f8_to_h8(a00, a01);
        *(uint4*)(Ah[0] + r1 * 80 + s1 * 16) = f8_to_h8(a10, a11);
        *(uint4*)(Bh[0] + r0 * 80 + s0 * 16) = *(const uint4*)wb0;
        *(uint4*)(Bh[0] + r1 * 80 + s1 * 16) = *(const uint4*)wb1;
    }
    __syncthreads();

    float acc[2][8][4] = {};

    for (int it = 0; it < 16; it++) {
        float4 a00, a01, a10, a11;
        uint4 pb0, pb1;
        if (it < 15) {
            const int kn = (it + 1) * 32;
            a00 = *(const float4*)(xa0 + kn);
            a01 = *(const float4*)(xa0 + kn + 4);
            a10 = *(const float4*)(xa1 + kn);
            a11 = *(const float4*)(xa1 + kn + 4);
            pb0 = *(const uint4*)(wb0 + kn);
            pb1 = *(const uint4*)(wb1 + kn);
        }
        const uint32_t Ab = AhA + (uint32_t)(it & 1) * (128 * 80);
        const uint32_t Bc = BhA + (uint32_t)(it & 1) * (128 * 80);
#pragma unroll
        for (int ks = 0; ks < 2; ks++) {
            uint32_t qa[2][4];
#pragma unroll
            for (int mt = 0; mt < 2; mt++)
                ldm4(qa[mt], Ab + (wm * 32 + mt * 16 + rowi + csel * 8) * 80
                              + ks * 32 + rsel * 16);
#pragma unroll
            for (int nb = 0; nb < 4; nb++) {
                uint32_t kb[4];
                ldm4(kb, Bc + (wn * 64 + nb * 16 + rowi + rsel * 8) * 80
                           + ks * 32 + csel * 16);
                mma16816(acc[0][nb * 2],     qa[0], kb[0], kb[1]);
                mma16816(acc[0][nb * 2 + 1], qa[0], kb[2], kb[3]);
                mma16816(acc[1][nb * 2],     qa[1], kb[0], kb[1]);
                mma16816(acc[1][nb * 2 + 1], qa[1], kb[2], kb[3]);
            }
        }
        if (it < 15) {
            char* An = Ah[(it + 1) & 1];
            char* Bn = Bh[(it + 1) & 1];
            *(uint4*)(An + r0 * 80 + s0 * 16) = f8_to_h8(a00, a01);
            *(uint4*)(An + r1 * 80 + s1 * 16) = f8_to_h8(a10, a11);
            *(uint4*)(Bn + r0 * 80 + s0 * 16) = pb0;
            *(uint4*)(Bn + r1 * 80 + s1 * 16) = pb1;
            __syncthreads();
        }
    }

    // epilogue
    const int b    = row0 >> 11;
    const int mloc = (row0 & (Mm - 1)) + wm * 32;

#pragma unroll
    for (int mt = 0; mt < 2; mt++) {
        const int ma = mloc + mt * 16 + g;
        float mka = 1.0f, mkb = 1.0f;
        if (col0 >= 256) {
            mka = (float)mask[b * Mm + ma];
            mkb = (float)mask[b * Mm + ma + 8];
        }
#pragma unroll
        for (int j = 0; j < 8; j++) {
            const int jg = col0 + wn * 64 + j * 8 + tig * 2;
            float c0 = acc[mt][j][0], c1 = acc[mt][j][1];
            float c2 = acc[mt][j][2], c3 = acc[mt][j][3];
            if (jg < 128) {
                const float b0 = bq[jg] * QSCALE, b1 = bq[jg + 1] * QSCALE;
                const int h = jg >> 4, dq = jg & 15;
                __half2 lo = __floats2half2_rn(c0 + b0, c1 + b1);
                __half2 hi = __floats2half2_rn(c2 + b0, c3 + b1);
                __half* base = &g_Qh[(((size_t)(b * Hh + h)) * Mm + ma) * 16 + dq];
                *(uint32_t*)base = *(uint32_t*)&lo;
                *(uint32_t*)(base + 8 * 16) = *(uint32_t*)&hi;
            } else if (jg < 256) {
                const int jj = jg - 128;
                const float b0 = bk[jj], b1 = bk[jj + 1];
                const int h = jj >> 4, dq = jj & 15;
                __half2 lo = __floats2half2_rn(c0 + b0, c1 + b1);
                __half2 hi = __floats2half2_rn(c2 + b0, c3 + b1);
                __half* base = &g_Kh[(((size_t)(b * Hh + h)) * Mm + ma) * 16 + dq];
                *(uint32_t*)base = *(uint32_t*)&lo;
                *(uint32_t*)(base + 8 * 16) = *(uint32_t*)&hi;
            } else {
                const int jj = jg - 256;
                const float b0 = bv[jj], b1 = bv[jj + 1];
                const int h = jj >> 6, d = jj & 63;
                __half* base = &g_VTh[(((size_t)(b * Hh + h)) * VTR + d) * Mm + ma];
                base[0]      = __float2half_rn((c0 + b0) * mka);
                base[Mm]     = __float2half_rn((c1 + b1) * mka);
                base[8]      = __float2half_rn((c2 + b0) * mkb);
                base[Mm + 8] = __float2half_rn((c3 + b1) * mkb);
            }
        }
    }
}

// ---------------------------------------------------------------------------
// Kernel 2: HMMA fp16 flash attention. Mask pre-folded into V; denominator
// computed by the PV MMA via the VT mask row. P = ex2(relu(s)) in f16x2.
// ---------------------------------------------------------------------------
#define KB 3072
#define VB 10368    // 72 rows * 144B

__global__ __launch_bounds__(128, 4) void attn_kernel(
    const float* __restrict__ gamma, float* __restrict__ out)
{
    __shared__ __align__(16) char Qs[128 * 48];
    __shared__ __align__(16) char Ks[2][64 * 48];
    __shared__ __align__(16) char Vs[2][VTR * 144];

    const int tid  = threadIdx.x;
    const int w    = tid >> 5;
    const int lane = tid & 31;
    const int g    = lane >> 2;
    const int tig  = lane & 3;

    const int bh = blockIdx.x >> 4;
    const int mt = blockIdx.x & 15;
    const int b  = bh >> 3;
    const int h  = bh & 7;
    const int m0 = mt * 128;

    const uint32_t QsA = smem_u32(Qs);
    const uint32_t KsA = smem_u32(Ks);
    const uint32_t VsA = smem_u32(Vs);

    {
        const uint4* q4 = (const uint4*)(g_Qh + ((size_t)bh * Mm + m0 + tid) * 16);
        *(uint4*)(Qs + tid * 48)      = q4[0];
        *(uint4*)(Qs + tid * 48 + 16) = q4[1];
    }

    // async tile issue
    const __half* vsrc0 = g_VTh + ((size_t)bh * VTR + (tid >> 1)) * Mm + (tid & 1) * 32;
    const uint32_t vdst0 = VsA + (uint32_t)((tid >> 1) * 144 + (tid & 1) * 64);
    const __half* esrc0 = g_VTh + ((size_t)bh * VTR + 64 + (tid >> 3)) * Mm + (tid & 7) * 8;
    const uint32_t edst0 = VsA + (uint32_t)((64 + (tid >> 3)) * 144 + (tid & 7) * 16);
    const __half* ksrc0 = g_Kh + ((size_t)bh * Mm + tid) * 16;
    const uint32_t kdst0 = KsA + (uint32_t)(tid * 48);

    auto issue_tile = [&](int nt, int buf) {
        const int n0 = nt * 64;
        const __half* vs = vsrc0 + n0;
        const uint32_t vd = vdst0 + (uint32_t)buf * VB;
        CP16(vd,      vs);
        CP16(vd + 16, vs + 8);
        CP16(vd + 32, vs + 16);
        CP16(vd + 48, vs + 24);
        if (tid < 64) {
            const __half* ks = ksrc0 + (size_t)n0 * 16;
            const uint32_t kd = kdst0 + (uint32_t)buf * KB;
            CP16(kd,      ks);
            CP16(kd + 16, ks + 8);
            CP16(edst0 + (uint32_t)buf * VB, esrc0 + n0);
        }
    };

    issue_tile(0, 0);
    CP_COMMIT();
    __syncthreads();   // Qs visible

    const int rsel = (lane >> 4) & 1;
    const int csel = (lane >> 3) & 1;
    const int rowi = (lane & 7);

    uint32_t qa[2][4];
#pragma unroll
    for (int mt2 = 0; mt2 < 2; mt2++)
        ldm4(qa[mt2], QsA + (w * 32 + mt2 * 16 + rowi + csel * 8) * 48 + rsel * 16);

    float o[2][8][4] = {};
    float oex[2][4] = {};

    const int knrow = rowi + rsel * 8;
    const int kcol  = csel * 16;
    const int ecol  = csel * 16;     // lanes 0-15 pattern for ldm2

    for (int nt = 0; nt < 32; nt++) {
        const int buf = nt & 1;
        if (nt + 1 < 32) {
            issue_tile(nt + 1, buf ^ 1);
            CP_COMMIT();
            CP_WAIT1();
        } else {
            CP_WAIT0();
        }
        __syncthreads();

        const uint32_t Kb = KsA + (uint32_t)buf * KB;
        const uint32_t Vb = VsA + (uint32_t)buf * VB;

#pragma unroll
        for (int kn = 0; kn < 4; kn++) {
            uint32_t kb[4];
            ldm4(kb, Kb + (kn * 16 + knrow) * 48 + kcol);

            uint32_t pa[2][4];
#pragma unroll
            for (int mt2 = 0; mt2 < 2; mt2++) {
                float c0[4] = {}, c1[4] = {};
                mma16816(c0, qa[mt2], kb[0], kb[1]);
                mma16816(c1, qa[mt2], kb[2], kb[3]);
                pa[mt2][0] = exp_relu_pack(c0[0], c0[1]);   // row g,   k0-7
                pa[mt2][1] = exp_relu_pack(c0[2], c0[3]);   // row g+8, k0-7
                pa[mt2][2] = exp_relu_pack(c1[0], c1[1]);   // row g,   k8-15
                pa[mt2][3] = exp_relu_pack(c1[2], c1[3]);   // row g+8, k8-15
            }

#pragma unroll
            for (int p = 0; p < 4; p++) {
                uint32_t vb[4];
                ldm4(vb, Vb + (p * 16 + knrow) * 144 + kn * 32 + kcol);
                mma16816(o[0][2 * p],     pa[0], vb[0], vb[1]);
                mma16816(o[0][2 * p + 1], pa[0], vb[2], vb[3]);
                mma16816(o[1][2 * p],     pa[1], vb[0], vb[1]);
                mma16816(o[1][2 * p + 1], pa[1], vb[2], vb[3]);
            }
            {   // denominator tile: VT rows 64-71 (row 64 = mask)
                uint32_t eb[2];
                ldm2(eb, Vb + (64 + rowi) * 144 + kn * 32 + ecol);
                mma16816(oex[0], pa[0], eb[0], eb[1]);
                mma16816(oex[1], pa[1], eb[0], eb[1]);
            }
        }
        __syncthreads();
    }

    const float gm = gamma[0];
    float inv[2][2];
#pragma unroll
    for (int mt2 = 0; mt2 < 2; mt2++) {
        const float d0 = __shfl_sync(0xFFFFFFFFu, oex[mt2][0], g << 2);
        const float d1 = __shfl_sync(0xFFFFFFFFu, oex[mt2][2], g << 2);
        inv[mt2][0] = gm / (d0 + 1e-12f);
        inv[mt2][1] = gm / (d1 + 1e-12f);
    }

#pragma unroll
    for (int mt2 = 0; mt2 < 2; mt2++) {
#pragma unroll
        for (int rh = 0; rh < 2; rh++) {
            const int m = m0 + w * 32 + mt2 * 16 + rh * 8 + g;
            float* op = out + ((size_t)b * Mm + m) * Cc + h * 64 + tig * 2;
            const float iv = inv[mt2][rh];
#pragma unroll
            for (int ntile = 0; ntile < 8; ntile++) {
                float2 v;
                v.x = o[mt2][ntile][rh * 2 + 0] * iv;
                v.y = o[mt2][ntile][rh * 2 + 1] * iv;
                *(float2*)(op + ntile * 8) = v;
            }
        }
    }
}

// ---------------------------------------------------------------------------
extern "C" void kernel_launch(void* const* d_in, const int* in_sizes, int n_in,
                              void* d_out, int out_size)
{
    const float* x     = (const float*)d_in[0];
    const int*   mask  = (const int*)  d_in[1];
    const float* Wq    = (const float*)d_in[2];
    const float* bq    = (const float*)d_in[3];
    const float* Wk    = (const float*)d_in[4];
    const float* bk    = (const float*)d_in[5];
    const float* Wv    = (const float*)d_in[6];
    const float* bv    = (const float*)d_in[7];
    const float* gamma = (const float*)d_in[8];
    float* out = (float*)d_out;

    conv_w_kernel<<<(768 * Cc + BHt * Mm) / 256, 256>>>(Wq, Wk, Wv, mask);

    dim3 pg((Bb * Mm) / 128, 6);
    proj_kernel<<<pg, 256>>>(x, mask, bq, bk, bv);

    attn_kernel<<<BHt * (Mm / 128), 128>>>(gamma, out);
}